// round 1
// baseline (speedup 1.0000x reference)
#include <cuda_runtime.h>

// Problem constants (fixed shapes from reference)
#define NB   4
#define DB   8
#define CB   3
#define RB   4          // scale^2
#define KK   5
#define HH   128
#define WW   128
#define HWSZ (HH * WW)
#define PADB 2
#define TW   32         // tile width  (block x)
#define TH   8          // tile height (block y)
#define SW_  (TW + 2 * PADB)   // 36
#define SH_  (TH + 2 * PADB)   // 12

__global__ __launch_bounds__(256, 6)
void adaptive_conv_ps_kernel(const float* __restrict__ burst,
                             const float* __restrict__ kernels,
                             float* __restrict__ out)
{
    __shared__ float s[CB][SH_][SW_];

    const int nd = blockIdx.z;              // 0..31 (n*8+d)
    const int h0 = blockIdx.y * TH;
    const int w0 = blockIdx.x * TW;
    const int tx = threadIdx.x;             // 0..31
    const int ty = threadIdx.y;             // 0..7
    const int tid = ty * 32 + tx;

    // ---- cooperative load of burst tile (3 channels, halo=2, zero-pad OOB) ----
    const float* bptr = burst + (size_t)nd * CB * HWSZ;
    #pragma unroll 3
    for (int idx = tid; idx < CB * SH_ * SW_; idx += 256) {
        int c   = idx / (SH_ * SW_);
        int rem = idx - c * (SH_ * SW_);
        int sh  = rem / SW_;
        int sw  = rem - sh * SW_;
        int gh  = h0 + sh - PADB;
        int gw  = w0 + sw - PADB;
        float v = 0.0f;
        if (gh >= 0 && gh < HH && gw >= 0 && gw < WW)
            v = bptr[c * HWSZ + gh * WW + gw];
        s[c][sh][sw] = v;
    }
    __syncthreads();

    const int h = h0 + ty;
    const int w = w0 + tx;

    float acc[CB][RB];
    #pragma unroll
    for (int c = 0; c < CB; c++)
        #pragma unroll
        for (int r = 0; r < RB; r++)
            acc[c][r] = 0.0f;

    // kernels layout: (nd, r, i, j, h, w) -> nd*100*HW + (r*25 + i*5 + j)*HW + h*W + w
    const float* kp = kernels + (size_t)nd * (RB * KK * KK) * HWSZ + (size_t)h * WW + w;

    // ---- main accumulation: 100 coalesced streaming loads, 300 FMAs ----
    #pragma unroll
    for (int i = 0; i < KK; i++) {
        #pragma unroll
        for (int j = 0; j < KK; j++) {
            const float b0 = s[0][ty + i][tx + j];
            const float b1 = s[1][ty + i][tx + j];
            const float b2 = s[2][ty + i][tx + j];
            #pragma unroll
            for (int r = 0; r < RB; r++) {
                const float kv = __ldg(kp + (size_t)(r * 25 + i * 5 + j) * HWSZ);
                acc[0][r] = fmaf(kv, b0, acc[0][r]);
                acc[1][r] = fmaf(kv, b1, acc[1][r]);
                acc[2][r] = fmaf(kv, b2, acc[2][r]);
            }
        }
    }

    // ---- fused pixel shuffle epilogue ----
    // out shape (nd, c, 2H, 2W); out[.., 2h+si, 2w+sj] = acc[c][si*2+sj]
    // adjacent sj pair -> one coalesced float2 store per (c, si)
    float2* o2 = reinterpret_cast<float2*>(out);
    #pragma unroll
    for (int c = 0; c < CB; c++) {
        #pragma unroll
        for (int si = 0; si < 2; si++) {
            const size_t row = ((size_t)(nd * CB + c) * (2 * HH) + (2 * h + si));
            o2[row * WW + w] = make_float2(acc[c][si * 2 + 0], acc[c][si * 2 + 1]);
        }
    }
}

extern "C" void kernel_launch(void* const* d_in, const int* in_sizes, int n_in,
                              void* d_out, int out_size)
{
    const float* burst   = (const float*)d_in[0];   // (4,8,3,128,128)
    const float* kernels = (const float*)d_in[1];   // (4,8,4,5,5,128,128)
    float* out = (float*)d_out;                     // (4,8,3,256,256)

    dim3 block(32, 8, 1);
    dim3 grid(WW / TW, HH / TH, NB * DB);           // (4, 16, 32) = 2048 blocks
    adaptive_conv_ps_kernel<<<grid, block>>>(burst, kernels, out);
}